// round 15
// baseline (speedup 1.0000x reference)
#include <cuda_runtime.h>
#include <cuda_bf16.h>
#include <math.h>
#include <string.h>
#include <stdint.h>

// ---------------------------------------------------------------------------
// Problem constants
// ---------------------------------------------------------------------------
#define BB 8
#define CC 128
#define HH 64
#define WW 64
#define UU 8
#define TOPK 2
#define LL 10
#define HID 128

#define HW (HH*WW)                       // 4096
#define N_FINAL (BB*CC*HW)               // 4194304
#define OFF_CLS  (N_FINAL)
#define OFF_L2   (N_FINAL + 80)
#define OFF_TOPI (N_FINAL + 81)
#define OFF_LB   (N_FINAL + 97)

#define KTOT 1152                        // 128 ci * 9
#define CH   36                          // K chunks of 32
#define AS_STRIDE 36
#define BUFSZ (128*AS_STRIDE)            // 4608 floats per tile buffer

// ---------------------------------------------------------------------------
// Device scratch
// ---------------------------------------------------------------------------
__device__ float g_stats[BB*CC*9];
__device__ float g_wsum[UU*CC*9];
__device__ float g_norms[12];
__device__ int   g_topi[BB*2];
__device__ float g_gate[BB*UU];
__device__ float g_beff[BB*CC];
__device__ float g_Weff[BB*CC*KTOT];     // 4.72 MB, [b][co][k] k-major

// TF32 rounding
__device__ __forceinline__ float tf32r(float v)
{
    uint32_t r;
    asm("cvt.rna.tf32.f32 %0, %1;" : "=r"(r) : "f"(v));
    float f;
    asm("mov.b32 %0, %1;" : "=f"(f) : "r"(r));
    return f;
}

// portable warp-level tf32 MMA (sm_80+)
__device__ __forceinline__ void mma168(float* d, const uint32_t* a, const uint32_t* bf)
{
    asm volatile(
        "mma.sync.aligned.m16n8k8.row.col.f32.tf32.tf32.f32 "
        "{%0,%1,%2,%3}, {%4,%5,%6,%7}, {%8,%9}, {%0,%1,%2,%3};"
        : "+f"(d[0]), "+f"(d[1]), "+f"(d[2]), "+f"(d[3])
        : "r"(a[0]), "r"(a[1]), "r"(a[2]), "r"(a[3]), "r"(bf[0]), "r"(bf[1]));
}

__device__ __forceinline__ void cp_async16(uint32_t smem_addr, const void* gptr)
{
    asm volatile("cp.async.ca.shared.global [%0], [%1], 16;"
                 :: "r"(smem_addr), "l"(gptr) : "memory");
}
__device__ __forceinline__ void cp_commit()
{
    asm volatile("cp.async.commit_group;" ::: "memory");
}
__device__ __forceinline__ void cp_wait0()
{
    asm volatile("cp.async.wait_group 0;" ::: "memory");
}

// ---------------------------------------------------------------------------
// K1 (fused pre-pass): [0,1024) stats; [1024,1064) wsum; [1064,1076) l2
// ---------------------------------------------------------------------------
struct L2Args { const float* p[12]; int n[12]; };

__global__ void __launch_bounds__(256) k_pre(const float* __restrict__ x,
                                             const float* __restrict__ conv_w,
                                             L2Args a)
{
    int blk = blockIdx.x;
    int t   = threadIdx.x;

    if (blk < 1024) {
        const float* base = x + (size_t)blk * HW;
        float T=0.f, r0=0.f, r63=0.f, c0=0.f, c63=0.f;
        for (int i = t; i < HW; i += 256) {
            float v = base[i];
            int y = i >> 6, xc = i & 63;
            T += v;
            if (y == 0)   r0  += v;
            if (y == 63)  r63 += v;
            if (xc == 0)  c0  += v;
            if (xc == 63) c63 += v;
        }
        #pragma unroll
        for (int off = 16; off; off >>= 1) {
            T   += __shfl_down_sync(0xffffffffu, T,   off);
            r0  += __shfl_down_sync(0xffffffffu, r0,  off);
            r63 += __shfl_down_sync(0xffffffffu, r63, off);
            c0  += __shfl_down_sync(0xffffffffu, c0,  off);
            c63 += __shfl_down_sync(0xffffffffu, c63, off);
        }
        __shared__ float red[8][5];
        if ((t & 31) == 0) {
            int w = t >> 5;
            red[w][0]=T; red[w][1]=r0; red[w][2]=r63; red[w][3]=c0; red[w][4]=c63;
        }
        __syncthreads();
        if (t == 0) {
            float s[5] = {0,0,0,0,0};
            for (int w = 0; w < 8; ++w)
                for (int k = 0; k < 5; ++k) s[k] += red[w][k];
            float* o = g_stats + (size_t)blk * 9;
            o[0]=s[0]; o[1]=s[1]; o[2]=s[2]; o[3]=s[3]; o[4]=s[4];
            o[5]=base[0]; o[6]=base[63]; o[7]=base[63*64]; o[8]=base[HW-1];
        }
    } else if (blk < 1064) {
        int q = blk - 1024;
        int u = q / 5;
        int idx = (q % 5) * 256 + t;
        if (idx < KTOT) {
            const float* base = conv_w + (size_t)u * CC * KTOT + idx;
            float s = 0.f;
            for (int co = 0; co < CC; ++co) s += base[(size_t)co * KTOT];
            g_wsum[u * KTOT + idx] = s;
        }
    } else {
        int bi = blk - 1064;
        const float* p = a.p[bi]; int n = a.n[bi];
        float s = 0.f;
        for (int i = t; i < n; i += 256) { float v = p[i]; s += v*v; }
        #pragma unroll
        for (int off = 16; off; off >>= 1) s += __shfl_down_sync(0xffffffffu, s, off);
        __shared__ float ws[8];
        if ((t & 31) == 0) ws[t >> 5] = s;
        __syncthreads();
        if (t == 0) {
            float tot = 0.f;
            for (int w = 0; w < 8; ++w) tot += ws[w];
            g_norms[bi] = sqrtf(tot);
        }
    }
}

// ---------------------------------------------------------------------------
// K2: router (1 block, 128 thr)
// ---------------------------------------------------------------------------
struct Noise64 { float v[64]; };

__global__ void k_router(const float* __restrict__ W1, const float* __restrict__ b1,
                         const float* __restrict__ W2, const float* __restrict__ b2,
                         const float* __restrict__ W3, const float* __restrict__ b3,
                         const float* __restrict__ W4, const float* __restrict__ b4,
                         const float* __restrict__ Wu, const float* __restrict__ bu,
                         const float* __restrict__ Wc, const float* __restrict__ bc,
                         const float* __restrict__ conv_b,
                         Noise64 nz, float* __restrict__ out)
{
    __shared__ float A[BB][HID];
    __shared__ float Bv[BB][HID];
    __shared__ float F[BB][64];
    __shared__ float S[BB][UU];
    __shared__ int   TI[BB][2];
    __shared__ float bsum_s[UU];
    __shared__ float m_s[BB][UU];
    __shared__ float part[16][128];
    __shared__ float wu_s[512];
    __shared__ float wc_s[640];
    __shared__ float cb_s[1024];

    int t = threadIdx.x;   // 128

    for (int i = t; i < 512;  i += 128) wu_s[i] = Wu[i];
    for (int i = t; i < 640;  i += 128) wc_s[i] = Wc[i];
    for (int i = t; i < 1024; i += 128) cb_s[i] = conv_b[i];
    for (int b = 0; b < BB; ++b)
        A[b][t] = g_stats[(size_t)(b*CC + t) * 9] * (1.0f/4096.0f);
    __syncthreads();

    // L1
    {
        const float4* Wv = (const float4*)W1;
        float acc[BB]; float bb = b1[t];
        #pragma unroll
        for (int b = 0; b < BB; ++b) acc[b] = bb;
        #pragma unroll 4
        for (int i = 0; i < 32; ++i) {
            float4 w = Wv[t*32 + i];
            int c = i*4;
            #pragma unroll
            for (int b = 0; b < BB; ++b) {
                acc[b] = fmaf(A[b][c+0], w.x, acc[b]);
                acc[b] = fmaf(A[b][c+1], w.y, acc[b]);
                acc[b] = fmaf(A[b][c+2], w.z, acc[b]);
                acc[b] = fmaf(A[b][c+3], w.w, acc[b]);
            }
        }
        #pragma unroll
        for (int b = 0; b < BB; ++b) Bv[b][t] = fmaxf(acc[b], 0.f);
    }
    __syncthreads();
    // L2
    {
        const float4* Wv = (const float4*)W2;
        float acc[BB]; float bb = b2[t];
        #pragma unroll
        for (int b = 0; b < BB; ++b) acc[b] = bb;
        #pragma unroll 4
        for (int i = 0; i < 32; ++i) {
            float4 w = Wv[t*32 + i];
            int c = i*4;
            #pragma unroll
            for (int b = 0; b < BB; ++b) {
                acc[b] = fmaf(Bv[b][c+0], w.x, acc[b]);
                acc[b] = fmaf(Bv[b][c+1], w.y, acc[b]);
                acc[b] = fmaf(Bv[b][c+2], w.z, acc[b]);
                acc[b] = fmaf(Bv[b][c+3], w.w, acc[b]);
            }
        }
        #pragma unroll
        for (int b = 0; b < BB; ++b) A[b][t] = fmaxf(acc[b], 0.f);
    }
    __syncthreads();
    // L3: 128 -> 64
    if (t < 64) {
        const float4* Wv = (const float4*)W3;
        float acc[BB]; float bb = b3[t];
        #pragma unroll
        for (int b = 0; b < BB; ++b) acc[b] = bb;
        #pragma unroll 4
        for (int i = 0; i < 32; ++i) {
            float4 w = Wv[t*32 + i];
            int c = i*4;
            #pragma unroll
            for (int b = 0; b < BB; ++b) {
                acc[b] = fmaf(A[b][c+0], w.x, acc[b]);
                acc[b] = fmaf(A[b][c+1], w.y, acc[b]);
                acc[b] = fmaf(A[b][c+2], w.z, acc[b]);
                acc[b] = fmaf(A[b][c+3], w.w, acc[b]);
            }
        }
        #pragma unroll
        for (int b = 0; b < BB; ++b) Bv[b][t] = fmaxf(acc[b], 0.f);
    }
    __syncthreads();
    // L4: 64 -> 64 (no relu)
    if (t < 64) {
        const float4* Wv = (const float4*)W4;
        float acc[BB]; float bb = b4[t];
        #pragma unroll
        for (int b = 0; b < BB; ++b) acc[b] = bb;
        #pragma unroll 4
        for (int i = 0; i < 16; ++i) {
            float4 w = Wv[t*16 + i];
            int c = i*4;
            #pragma unroll
            for (int b = 0; b < BB; ++b) {
                acc[b] = fmaf(Bv[b][c+0], w.x, acc[b]);
                acc[b] = fmaf(Bv[b][c+1], w.y, acc[b]);
                acc[b] = fmaf(Bv[b][c+2], w.z, acc[b]);
                acc[b] = fmaf(Bv[b][c+3], w.w, acc[b]);
            }
        }
        #pragma unroll
        for (int b = 0; b < BB; ++b) F[b][t] = acc[b];
    }
    __syncthreads();

    if (t < BB*UU) {
        int b = t >> 3, u = t & 7;
        float a = bu[u] + nz.v[t];
        for (int c = 0; c < 64; ++c) a = fmaf(F[b][c], wu_s[u*64 + c], a);
        S[b][u] = a;
    }
    if (t < BB*LL) {
        int b = t / LL, l = t % LL;
        float a = bc[l];
        for (int c = 0; c < 64; ++c) a = fmaf(F[b][c], wc_s[l*64 + c], a);
        out[OFF_CLS + t] = a;
    }
    if (t >= 96 && t < 96 + UU) {
        int u = t - 96;
        float s = 0.f;
        for (int c = 0; c < CC; ++c) s += cb_s[u*CC + c];
        bsum_s[u] = s;
    }
    __syncthreads();

    if (t < BB) {
        int b = t;
        int i0 = 0; float v0 = S[b][0];
        for (int u = 1; u < UU; ++u) if (S[b][u] > v0) { v0 = S[b][u]; i0 = u; }
        int i1 = -1; float v1 = -3.4e38f;
        for (int u = 0; u < UU; ++u) if (u != i0 && S[b][u] > v1) { v1 = S[b][u]; i1 = u; }
        TI[b][0] = i0;  TI[b][1] = i1;
        g_topi[b*2] = i0;  g_topi[b*2+1] = i1;
        out[OFF_TOPI + b*2]     = (float)i0;
        out[OFF_TOPI + b*2 + 1] = (float)i1;
    }
    __syncthreads();

    if (t == 0) {
        int cnt[UU] = {0,0,0,0,0,0,0,0};
        for (int b = 0; b < BB; ++b) { cnt[TI[b][0]]++; cnt[TI[b][1]]++; }
        float lb = 0.f;
        for (int u = 0; u < UU; ++u) {
            float d = (float)cnt[u] * (1.0f/16.0f) - 0.125f;
            lb += d*d;
        }
        out[OFF_LB] = lb * (1.0f/8.0f);
        float s = 0.f;
        for (int i = 0; i < 12; ++i) s += g_norms[i];
        out[OFF_L2] = 0.01f * s;
    }
    if (t < BB*UU) m_s[t>>3][t&7] = bsum_s[t&7] * (1.0f/128.0f);

    for (int b = 0; b < BB; ++b) {
        const float* st = g_stats + (size_t)(b*CC + t) * 9;
        float T  = st[0], R0 = st[1], R63 = st[2], C0 = st[3], C63 = st[4];
        float x00 = st[5], x0e = st[6], xe0 = st[7], xee = st[8];
        float Sv[9];
        #pragma unroll
        for (int dy = 0; dy < 3; ++dy)
            #pragma unroll
            for (int dx = 0; dx < 3; ++dx) {
                float s = T;
                if (dy == 0) s -= R63;
                if (dy == 2) s -= R0;
                if (dx == 0) s -= C63;
                if (dx == 2) s -= C0;
                if (dy == 0 && dx == 0) s += xee;
                if (dy == 0 && dx == 2) s += xe0;
                if (dy == 2 && dx == 0) s += x0e;
                if (dy == 2 && dx == 2) s += x00;
                Sv[dy*3 + dx] = s;
            }
        #pragma unroll
        for (int j = 0; j < 2; ++j) {
            int u = TI[b][j];
            const float* wr = g_wsum + (size_t)u * KTOT + t*9;
            float p = 0.f;
            #pragma unroll
            for (int k = 0; k < 9; ++k) p = fmaf(wr[k], Sv[k], p);
            part[b*2 + j][t] = p;
        }
    }
    __syncthreads();

    {
        int w = t >> 5, l = t & 31;
        #pragma unroll
        for (int q = 0; q < 4; ++q) {
            int pr = w*4 + q;
            float s = part[pr][l] + part[pr][l+32] + part[pr][l+64] + part[pr][l+96];
            #pragma unroll
            for (int off = 16; off; off >>= 1) s += __shfl_down_sync(0xffffffffu, s, off);
            if (l == 0) {
                int bb2 = pr >> 1, jj = pr & 1;
                int u = TI[bb2][jj];
                m_s[bb2][u] += s * (1.0f/524288.0f);
            }
        }
    }
    __syncthreads();

    if (t < BB) {
        int b = t;
        float mx = -3.4e38f;
        for (int u = 0; u < UU; ++u) mx = fmaxf(mx, m_s[b][u]);
        float e[UU], s = 0.f;
        for (int u = 0; u < UU; ++u) { e[u] = expf(m_s[b][u] - mx); s += e[u]; }
        for (int u = 0; u < UU; ++u) g_gate[b*UU + u] = e[u] / s;
    }
}

// ---------------------------------------------------------------------------
// K3: W_eff + b_eff
// ---------------------------------------------------------------------------
__global__ void k_weff(const float* __restrict__ conv_w, const float* __restrict__ conv_b)
{
    int b  = blockIdx.x >> 7;
    int co = blockIdx.x & 127;
    int t  = threadIdx.x;          // 128
    int u0 = g_topi[b*2], u1 = g_topi[b*2+1];
    float g0 = g_gate[b*UU + u0], g1 = g_gate[b*UU + u1];
    const float* w0 = conv_w + (size_t)(u0*CC + co) * KTOT;
    const float* w1 = conv_w + (size_t)(u1*CC + co) * KTOT;
    float* dst = g_Weff + (size_t)(b*CC + co) * KTOT;
    #pragma unroll
    for (int j = 0; j < 9; ++j) {
        int k = j*128 + t;
        dst[k] = tf32r(g0 * tf32r(w0[k]) + g1 * tf32r(w1[k]));
    }
    if (t == 0) {
        float s = 0.f;
        for (int u = 0; u < UU; ++u) s += g_gate[b*UU + u] * conv_b[u*CC + co];
        g_beff[b*CC + co] = s;
    }
}

// ---------------------------------------------------------------------------
// K4: tf32 mma.sync implicit-GEMM conv, double-buffered + cp.async pipeline
// grid 256 = 8 b x 32 tiles (128 px); 256 thr = 8 warps (2m x 4n)
// dynamic smem: A[2][4608] + B[2][4608] floats = 73728 B
// ---------------------------------------------------------------------------
__global__ void __launch_bounds__(256, 2) k_conv_mma(const float* __restrict__ xg,
                                                     float* __restrict__ out)
{
    extern __shared__ float sm[];
    float* Abuf[2] = { sm,            sm + BUFSZ   };
    float* Bbuf[2] = { sm + 2*BUFSZ,  sm + 3*BUFSZ };

    int tid  = threadIdx.x;
    int lane = tid & 31, wid = tid >> 5;
    int b    = blockIdx.x >> 5;
    int tile = blockIdx.x & 31;
    int warp_m = wid >> 2;
    int warp_n = wid & 3;
    int gid = lane >> 2, tig = lane & 3;

    const float* xb = xg + (size_t)b * (CC*HW);
    const float* Wb = g_Weff + (size_t)b * (CC*KTOT);

    int n  = tid & 127;
    int kh = tid >> 7;
    int py = tile*2 + (n >> 6);
    int px = n & 63;

    float d[16][4];
    #pragma unroll
    for (int i = 0; i < 16; ++i)
        #pragma unroll
        for (int j = 0; j < 4; ++j) d[i][j] = 0.f;

    // ---- A stage via cp.async (4 x 16B per thread) ----
    auto stageA = [&](int c, float* dst) {
        uint32_t sbase = (uint32_t)__cvta_generic_to_shared(dst);
        #pragma unroll
        for (int i = 0; i < 4; ++i) {
            int e   = tid*4 + i;
            int co  = e >> 3;
            int seg = e & 7;
            cp_async16(sbase + (uint32_t)(co*AS_STRIDE + seg*4)*4u,
                       Wb + (size_t)co*KTOT + c*32 + seg*4);
        }
        cp_commit();
    };

    // ---- B gather: 16 raw values for chunk c into regs ----
    auto gatherB = [&](int c, float* bv) {
        int k0 = c*32 + kh*16;
        int ci = (k0 * 7282) >> 16;          // k0/9
        int r  = k0 - ci*9;
        #pragma unroll
        for (int e = 0; e < 16; ++e) {
            int dy = (r * 11) >> 5;          // r/3
            int dx = r - dy*3 - 1;
            dy -= 1;
            int yy = py + dy, xx = px + dx;
            float val = 0.f;
            if ((unsigned)yy < 64u && (unsigned)xx < 64u)
                val = xb[((size_t)ci << 12) + (yy << 6) + xx];
            bv[e] = val;
            if (++r == 9) { r = 0; ++ci; }
        }
    };

    auto storeB = [&](float* bv, float* dst) {
        #pragma unroll
        for (int g = 0; g < 4; ++g)
            *(float4*)(dst + n*AS_STRIDE + kh*16 + g*4) =
                make_float4(tf32r(bv[g*4+0]), tf32r(bv[g*4+1]),
                            tf32r(bv[g*4+2]), tf32r(bv[g*4+3]));
    };

    // ---- prologue: produce chunk 0 into buffer 0 ----
    {
        float bv[16];
        stageA(0, Abuf[0]);
        gatherB(0, bv);
        storeB(bv, Bbuf[0]);
        cp_wait0();
    }
    __syncthreads();

    #pragma unroll 1
    for (int c = 0; c < CH; ++c) {
        int s = c & 1;
        float bv[16];
        if (c < CH-1) {
            stageA(c+1, Abuf[1-s]);          // async, no wait
            gatherB(c+1, bv);                // LDGs in flight over MMA below
        }

        // ---- MMA over chunk c ----
        const float* As = Abuf[s];
        const float* Bs = Bbuf[s];
        #pragma unroll
        for (int ks = 0; ks < 4; ++ks) {
            uint32_t af[4][4];
            #pragma unroll
            for (int mt = 0; mt < 4; ++mt) {
                int row = warp_m*64 + mt*16 + gid;
                int col = ks*8 + tig;
                af[mt][0] = __float_as_uint(As[row*AS_STRIDE + col]);
                af[mt][1] = __float_as_uint(As[(row+8)*AS_STRIDE + col]);
                af[mt][2] = __float_as_uint(As[row*AS_STRIDE + col + 4]);
                af[mt][3] = __float_as_uint(As[(row+8)*AS_STRIDE + col + 4]);
            }
            uint32_t bf[4][2];
            #pragma unroll
            for (int nt = 0; nt < 4; ++nt) {
                int nn = warp_n*32 + nt*8 + gid;
                int kk = ks*8 + tig;
                bf[nt][0] = __float_as_uint(Bs[nn*AS_STRIDE + kk]);
                bf[nt][1] = __float_as_uint(Bs[nn*AS_STRIDE + kk + 4]);
            }
            #pragma unroll
            for (int mt = 0; mt < 4; ++mt)
                #pragma unroll
                for (int nt = 0; nt < 4; ++nt)
                    mma168(d[mt*4 + nt], af[mt], bf[nt]);
        }

        if (c < CH-1) {
            storeB(bv, Bbuf[1-s]);
            cp_wait0();
        }
        __syncthreads();
    }

    // epilogue
    #pragma unroll
    for (int mt = 0; mt < 4; ++mt) {
        int co = warp_m*64 + mt*16 + gid;
        float be0 = g_beff[b*CC + co];
        float be8 = g_beff[b*CC + co + 8];
        #pragma unroll
        for (int nt = 0; nt < 4; ++nt) {
            int col = warp_n*32 + nt*8 + tig*2;
            float* op = out + (size_t)(b*CC + co) * HW + tile*128 + col;
            *(float2*)op = make_float2(d[mt*4+nt][0] + be0, d[mt*4+nt][1] + be0);
            *(float2*)(op + 8*HW) = make_float2(d[mt*4+nt][2] + be8, d[mt*4+nt][3] + be8);
        }
    }
}

// ---------------------------------------------------------------------------
// Host: JAX threefry2x32 noise (partitionable), key(42)
// ---------------------------------------------------------------------------
static inline uint32_t rotl32(uint32_t x, int d) { return (x << d) | (x >> (32 - d)); }

static void threefry2x32_host(uint32_t k0, uint32_t k1, uint32_t x0, uint32_t x1,
                              uint32_t* o0, uint32_t* o1)
{
    const uint32_t ks0 = k0, ks1 = k1, ks2 = k0 ^ k1 ^ 0x1BD11BDAu;
    const int ra[4] = {13, 15, 26, 6};
    const int rb[4] = {17, 29, 16, 24};
    x0 += ks0; x1 += ks1;
    for (int i = 0; i < 4; ++i) { x0 += x1; x1 = rotl32(x1, ra[i]); x1 ^= x0; }
    x0 += ks1; x1 += ks2 + 1u;
    for (int i = 0; i < 4; ++i) { x0 += x1; x1 = rotl32(x1, rb[i]); x1 ^= x0; }
    x0 += ks2; x1 += ks0 + 2u;
    for (int i = 0; i < 4; ++i) { x0 += x1; x1 = rotl32(x1, ra[i]); x1 ^= x0; }
    x0 += ks0; x1 += ks1 + 3u;
    for (int i = 0; i < 4; ++i) { x0 += x1; x1 = rotl32(x1, rb[i]); x1 ^= x0; }
    x0 += ks1; x1 += ks2 + 4u;
    for (int i = 0; i < 4; ++i) { x0 += x1; x1 = rotl32(x1, ra[i]); x1 ^= x0; }
    x0 += ks2; x1 += ks0 + 5u;
    *o0 = x0; *o1 = x1;
}

static double erfinv_host(double x)
{
    double p;
    double ww = -log((1.0 - x) * (1.0 + x));
    if (ww < 5.0) {
        ww -= 2.5;
        p = 2.81022636e-08;        p = 3.43273939e-07 + p*ww;
        p = -3.5233877e-06 + p*ww; p = -4.39150654e-06 + p*ww;
        p = 0.00021858087 + p*ww;  p = -0.00125372503 + p*ww;
        p = -0.00417768164 + p*ww; p = 0.246640727 + p*ww;
        p = 1.50140941 + p*ww;
    } else {
        ww = sqrt(ww) - 3.0;
        p = -0.000200214257;       p = 0.000100950558 + p*ww;
        p = 0.00134934322 + p*ww;  p = -0.00367342844 + p*ww;
        p = 0.00573950773 + p*ww;  p = -0.0076224613 + p*ww;
        p = 0.00943887047 + p*ww;  p = 1.00167406 + p*ww;
        p = 2.83297682 + p*ww;
    }
    return p * x;
}

static void compute_noise(float* noise /*64*/)
{
    float lo = nextafterf(-1.0f, 0.0f);
    float range = 1.0f - lo;
    for (uint32_t i = 0; i < 64; ++i) {
        uint32_t o0, o1;
        threefry2x32_host(0u, 42u, 0u, i, &o0, &o1);
        uint32_t bits = o0 ^ o1;
        uint32_t fb = (bits >> 9) | 0x3f800000u;
        float f; memcpy(&f, &fb, 4);
        f -= 1.0f;
        float u = f * range + lo;
        if (u < lo) u = lo;
        double z = erfinv_host((double)u);
        noise[i] = (float)(sqrt(2.0) * z) * 0.01f;
    }
}

// ---------------------------------------------------------------------------
// Entry — inputs resolved BY SIZE
// ---------------------------------------------------------------------------
static const float* find_by_size(void* const* d_in, const int* in_sizes, int n_in,
                                 int want, int occurrence)
{
    int seen = 0;
    for (int i = 0; i < n_in; ++i) {
        if (in_sizes[i] == want) {
            if (seen == occurrence) return (const float*)d_in[i];
            ++seen;
        }
    }
    return nullptr;
}

extern "C" void kernel_launch(void* const* d_in, const int* in_sizes, int n_in,
                              void* d_out, int out_size)
{
    const float* x      = find_by_size(d_in, in_sizes, n_in, BB*CC*HW, 0);
    const float* W1     = find_by_size(d_in, in_sizes, n_in, 16384, 0);
    const float* W2     = find_by_size(d_in, in_sizes, n_in, 16384, 1);
    const float* b1     = find_by_size(d_in, in_sizes, n_in, 128, 0);
    const float* b2     = find_by_size(d_in, in_sizes, n_in, 128, 1);
    const float* W3     = find_by_size(d_in, in_sizes, n_in, 8192, 0);
    const float* b3     = find_by_size(d_in, in_sizes, n_in, 64, 0);
    const float* W4     = find_by_size(d_in, in_sizes, n_in, 4096, 0);
    const float* b4     = find_by_size(d_in, in_sizes, n_in, 64, 1);
    const float* Wu     = find_by_size(d_in, in_sizes, n_in, 512, 0);
    const float* bu     = find_by_size(d_in, in_sizes, n_in, 8, 0);
    const float* Wc     = find_by_size(d_in, in_sizes, n_in, 640, 0);
    const float* bc     = find_by_size(d_in, in_sizes, n_in, 10, 0);
    const float* conv_w = find_by_size(d_in, in_sizes, n_in, UU*CC*CC*9, 0);
    const float* conv_b = find_by_size(d_in, in_sizes, n_in, 1024, 0);
    float* out = (float*)d_out;

    if (!x || !W1 || !W2 || !b1 || !b2 || !W3 || !b3 || !W4 || !b4 ||
        !Wu || !bu || !Wc || !bc || !conv_w || !conv_b) {
        x = (const float*)d_in[0];
        W1 = (const float*)d_in[1];  b1 = (const float*)d_in[2];
        W2 = (const float*)d_in[3];  b2 = (const float*)d_in[4];
        W3 = (const float*)d_in[5];  b3 = (const float*)d_in[6];
        W4 = (const float*)d_in[7];  b4 = (const float*)d_in[8];
        Wu = (const float*)d_in[9];  bu = (const float*)d_in[10];
        Wc = (const float*)d_in[11]; bc = (const float*)d_in[12];
        conv_w = (const float*)d_in[13]; conv_b = (const float*)d_in[14];
    }

    Noise64 nz;
    compute_noise(nz.v);

    L2Args la;
    const float* l2p[12] = {W1,b1,W2,b2,W3,b3,W4,b4,Wu,bu,Wc,bc};
    const int    l2n[12] = {16384,128,16384,128,8192,64,4096,64,512,8,640,10};
    for (int i = 0; i < 12; ++i) { la.p[i] = l2p[i]; la.n[i] = l2n[i]; }

    cudaFuncSetAttribute(k_conv_mma, cudaFuncAttributeMaxDynamicSharedMemorySize,
                         4*BUFSZ*sizeof(float));

    k_pre<<<1076, 256>>>(x, conv_w, la);
    k_router<<<1, 128>>>(W1, b1, W2, b2, W3, b3, W4, b4,
                         Wu, bu, Wc, bc, conv_b, nz, out);
    k_weff<<<1024, 128>>>(conv_w, conv_b);
    k_conv_mma<<<256, 256, 4*BUFSZ*sizeof(float)>>>(x, out);
}

// round 16
// speedup vs baseline: 1.0578x; 1.0578x over previous
#include <cuda_runtime.h>
#include <cuda_bf16.h>
#include <math.h>
#include <string.h>
#include <stdint.h>

// ---------------------------------------------------------------------------
// Problem constants
// ---------------------------------------------------------------------------
#define BB 8
#define CC 128
#define HH 64
#define WW 64
#define UU 8
#define TOPK 2
#define LL 10
#define HID 128

#define HW (HH*WW)                       // 4096
#define N_FINAL (BB*CC*HW)               // 4194304
#define OFF_CLS  (N_FINAL)
#define OFF_L2   (N_FINAL + 80)
#define OFF_TOPI (N_FINAL + 81)
#define OFF_LB   (N_FINAL + 97)

#define KTOT 1152                        // 128 ci * 9
#define CH   36                          // K chunks of 32
#define SS   40                          // smem row stride (pad 32 -> 40)

// ---------------------------------------------------------------------------
// Device scratch
// ---------------------------------------------------------------------------
__device__ float g_stats[BB*CC*9];
__device__ float g_wsum[UU*CC*9];
__device__ float g_norms[12];
__device__ int   g_topi[BB*2];
__device__ float g_gate[BB*UU];
__device__ float g_beff[BB*CC];
__device__ float g_Weff[BB*CC*KTOT];     // 4.72 MB, [b][co][k] — k PERMUTED per 8-group

// TF32 rounding
__device__ __forceinline__ float tf32r(float v)
{
    uint32_t r;
    asm("cvt.rna.tf32.f32 %0, %1;" : "=r"(r) : "f"(v));
    float f;
    asm("mov.b32 %0, %1;" : "=f"(f) : "r"(r));
    return f;
}

// portable warp-level tf32 MMA (sm_80+)
__device__ __forceinline__ void mma168(float* d, const uint32_t* a, const uint32_t* bf)
{
    asm volatile(
        "mma.sync.aligned.m16n8k8.row.col.f32.tf32.tf32.f32 "
        "{%0,%1,%2,%3}, {%4,%5,%6,%7}, {%8,%9}, {%0,%1,%2,%3};"
        : "+f"(d[0]), "+f"(d[1]), "+f"(d[2]), "+f"(d[3])
        : "r"(a[0]), "r"(a[1]), "r"(a[2]), "r"(a[3]), "r"(bf[0]), "r"(bf[1]));
}

// ---------------------------------------------------------------------------
// K1 (fused pre-pass): [0,1024) stats; [1024,1064) wsum; [1064,1076) l2
// ---------------------------------------------------------------------------
struct L2Args { const float* p[12]; int n[12]; };

__global__ void __launch_bounds__(256) k_pre(const float* __restrict__ x,
                                             const float* __restrict__ conv_w,
                                             L2Args a)
{
    int blk = blockIdx.x;
    int t   = threadIdx.x;

    if (blk < 1024) {
        const float* base = x + (size_t)blk * HW;
        float T=0.f, r0=0.f, r63=0.f, c0=0.f, c63=0.f;
        for (int i = t; i < HW; i += 256) {
            float v = base[i];
            int y = i >> 6, xc = i & 63;
            T += v;
            if (y == 0)   r0  += v;
            if (y == 63)  r63 += v;
            if (xc == 0)  c0  += v;
            if (xc == 63) c63 += v;
        }
        #pragma unroll
        for (int off = 16; off; off >>= 1) {
            T   += __shfl_down_sync(0xffffffffu, T,   off);
            r0  += __shfl_down_sync(0xffffffffu, r0,  off);
            r63 += __shfl_down_sync(0xffffffffu, r63, off);
            c0  += __shfl_down_sync(0xffffffffu, c0,  off);
            c63 += __shfl_down_sync(0xffffffffu, c63, off);
        }
        __shared__ float red[8][5];
        if ((t & 31) == 0) {
            int w = t >> 5;
            red[w][0]=T; red[w][1]=r0; red[w][2]=r63; red[w][3]=c0; red[w][4]=c63;
        }
        __syncthreads();
        if (t == 0) {
            float s[5] = {0,0,0,0,0};
            for (int w = 0; w < 8; ++w)
                for (int k = 0; k < 5; ++k) s[k] += red[w][k];
            float* o = g_stats + (size_t)blk * 9;
            o[0]=s[0]; o[1]=s[1]; o[2]=s[2]; o[3]=s[3]; o[4]=s[4];
            o[5]=base[0]; o[6]=base[63]; o[7]=base[63*64]; o[8]=base[HW-1];
        }
    } else if (blk < 1064) {
        int q = blk - 1024;
        int u = q / 5;
        int idx = (q % 5) * 256 + t;
        if (idx < KTOT) {
            const float* base = conv_w + (size_t)u * CC * KTOT + idx;
            float s = 0.f;
            for (int co = 0; co < CC; ++co) s += base[(size_t)co * KTOT];
            g_wsum[u * KTOT + idx] = s;
        }
    } else {
        int bi = blk - 1064;
        const float* p = a.p[bi]; int n = a.n[bi];
        float s = 0.f;
        for (int i = t; i < n; i += 256) { float v = p[i]; s += v*v; }
        #pragma unroll
        for (int off = 16; off; off >>= 1) s += __shfl_down_sync(0xffffffffu, s, off);
        __shared__ float ws[8];
        if ((t & 31) == 0) ws[t >> 5] = s;
        __syncthreads();
        if (t == 0) {
            float tot = 0.f;
            for (int w = 0; w < 8; ++w) tot += ws[w];
            g_norms[bi] = sqrtf(tot);
        }
    }
}

// ---------------------------------------------------------------------------
// K2: router (1 block, 128 thr)
// ---------------------------------------------------------------------------
struct Noise64 { float v[64]; };

__global__ void k_router(const float* __restrict__ W1, const float* __restrict__ b1,
                         const float* __restrict__ W2, const float* __restrict__ b2,
                         const float* __restrict__ W3, const float* __restrict__ b3,
                         const float* __restrict__ W4, const float* __restrict__ b4,
                         const float* __restrict__ Wu, const float* __restrict__ bu,
                         const float* __restrict__ Wc, const float* __restrict__ bc,
                         const float* __restrict__ conv_b,
                         Noise64 nz, float* __restrict__ out)
{
    __shared__ float A[BB][HID];
    __shared__ float Bv[BB][HID];
    __shared__ float F[BB][64];
    __shared__ float S[BB][UU];
    __shared__ int   TI[BB][2];
    __shared__ float bsum_s[UU];
    __shared__ float m_s[BB][UU];
    __shared__ float part[16][128];
    __shared__ float wu_s[512];
    __shared__ float wc_s[640];
    __shared__ float cb_s[1024];

    int t = threadIdx.x;   // 128

    for (int i = t; i < 512;  i += 128) wu_s[i] = Wu[i];
    for (int i = t; i < 640;  i += 128) wc_s[i] = Wc[i];
    for (int i = t; i < 1024; i += 128) cb_s[i] = conv_b[i];
    for (int b = 0; b < BB; ++b)
        A[b][t] = g_stats[(size_t)(b*CC + t) * 9] * (1.0f/4096.0f);
    __syncthreads();

    // L1
    {
        const float4* Wv = (const float4*)W1;
        float acc[BB]; float bb = b1[t];
        #pragma unroll
        for (int b = 0; b < BB; ++b) acc[b] = bb;
        #pragma unroll 4
        for (int i = 0; i < 32; ++i) {
            float4 w = Wv[t*32 + i];
            int c = i*4;
            #pragma unroll
            for (int b = 0; b < BB; ++b) {
                acc[b] = fmaf(A[b][c+0], w.x, acc[b]);
                acc[b] = fmaf(A[b][c+1], w.y, acc[b]);
                acc[b] = fmaf(A[b][c+2], w.z, acc[b]);
                acc[b] = fmaf(A[b][c+3], w.w, acc[b]);
            }
        }
        #pragma unroll
        for (int b = 0; b < BB; ++b) Bv[b][t] = fmaxf(acc[b], 0.f);
    }
    __syncthreads();
    // L2
    {
        const float4* Wv = (const float4*)W2;
        float acc[BB]; float bb = b2[t];
        #pragma unroll
        for (int b = 0; b < BB; ++b) acc[b] = bb;
        #pragma unroll 4
        for (int i = 0; i < 32; ++i) {
            float4 w = Wv[t*32 + i];
            int c = i*4;
            #pragma unroll
            for (int b = 0; b < BB; ++b) {
                acc[b] = fmaf(Bv[b][c+0], w.x, acc[b]);
                acc[b] = fmaf(Bv[b][c+1], w.y, acc[b]);
                acc[b] = fmaf(Bv[b][c+2], w.z, acc[b]);
                acc[b] = fmaf(Bv[b][c+3], w.w, acc[b]);
            }
        }
        #pragma unroll
        for (int b = 0; b < BB; ++b) A[b][t] = fmaxf(acc[b], 0.f);
    }
    __syncthreads();
    // L3: 128 -> 64
    if (t < 64) {
        const float4* Wv = (const float4*)W3;
        float acc[BB]; float bb = b3[t];
        #pragma unroll
        for (int b = 0; b < BB; ++b) acc[b] = bb;
        #pragma unroll 4
        for (int i = 0; i < 32; ++i) {
            float4 w = Wv[t*32 + i];
            int c = i*4;
            #pragma unroll
            for (int b = 0; b < BB; ++b) {
                acc[b] = fmaf(A[b][c+0], w.x, acc[b]);
                acc[b] = fmaf(A[b][c+1], w.y, acc[b]);
                acc[b] = fmaf(A[b][c+2], w.z, acc[b]);
                acc[b] = fmaf(A[b][c+3], w.w, acc[b]);
            }
        }
        #pragma unroll
        for (int b = 0; b < BB; ++b) Bv[b][t] = fmaxf(acc[b], 0.f);
    }
    __syncthreads();
    // L4: 64 -> 64 (no relu)
    if (t < 64) {
        const float4* Wv = (const float4*)W4;
        float acc[BB]; float bb = b4[t];
        #pragma unroll
        for (int b = 0; b < BB; ++b) acc[b] = bb;
        #pragma unroll 4
        for (int i = 0; i < 16; ++i) {
            float4 w = Wv[t*16 + i];
            int c = i*4;
            #pragma unroll
            for (int b = 0; b < BB; ++b) {
                acc[b] = fmaf(Bv[b][c+0], w.x, acc[b]);
                acc[b] = fmaf(Bv[b][c+1], w.y, acc[b]);
                acc[b] = fmaf(Bv[b][c+2], w.z, acc[b]);
                acc[b] = fmaf(Bv[b][c+3], w.w, acc[b]);
            }
        }
        #pragma unroll
        for (int b = 0; b < BB; ++b) F[b][t] = acc[b];
    }
    __syncthreads();

    if (t < BB*UU) {
        int b = t >> 3, u = t & 7;
        float a = bu[u] + nz.v[t];
        for (int c = 0; c < 64; ++c) a = fmaf(F[b][c], wu_s[u*64 + c], a);
        S[b][u] = a;
    }
    if (t < BB*LL) {
        int b = t / LL, l = t % LL;
        float a = bc[l];
        for (int c = 0; c < 64; ++c) a = fmaf(F[b][c], wc_s[l*64 + c], a);
        out[OFF_CLS + t] = a;
    }
    if (t >= 96 && t < 96 + UU) {
        int u = t - 96;
        float s = 0.f;
        for (int c = 0; c < CC; ++c) s += cb_s[u*CC + c];
        bsum_s[u] = s;
    }
    __syncthreads();

    if (t < BB) {
        int b = t;
        int i0 = 0; float v0 = S[b][0];
        for (int u = 1; u < UU; ++u) if (S[b][u] > v0) { v0 = S[b][u]; i0 = u; }
        int i1 = -1; float v1 = -3.4e38f;
        for (int u = 0; u < UU; ++u) if (u != i0 && S[b][u] > v1) { v1 = S[b][u]; i1 = u; }
        TI[b][0] = i0;  TI[b][1] = i1;
        g_topi[b*2] = i0;  g_topi[b*2+1] = i1;
        out[OFF_TOPI + b*2]     = (float)i0;
        out[OFF_TOPI + b*2 + 1] = (float)i1;
    }
    __syncthreads();

    if (t == 0) {
        int cnt[UU] = {0,0,0,0,0,0,0,0};
        for (int b = 0; b < BB; ++b) { cnt[TI[b][0]]++; cnt[TI[b][1]]++; }
        float lb = 0.f;
        for (int u = 0; u < UU; ++u) {
            float d = (float)cnt[u] * (1.0f/16.0f) - 0.125f;
            lb += d*d;
        }
        out[OFF_LB] = lb * (1.0f/8.0f);
        float s = 0.f;
        for (int i = 0; i < 12; ++i) s += g_norms[i];
        out[OFF_L2] = 0.01f * s;
    }
    if (t < BB*UU) m_s[t>>3][t&7] = bsum_s[t&7] * (1.0f/128.0f);

    for (int b = 0; b < BB; ++b) {
        const float* st = g_stats + (size_t)(b*CC + t) * 9;
        float T  = st[0], R0 = st[1], R63 = st[2], C0 = st[3], C63 = st[4];
        float x00 = st[5], x0e = st[6], xe0 = st[7], xee = st[8];
        float Sv[9];
        #pragma unroll
        for (int dy = 0; dy < 3; ++dy)
            #pragma unroll
            for (int dx = 0; dx < 3; ++dx) {
                float s = T;
                if (dy == 0) s -= R63;
                if (dy == 2) s -= R0;
                if (dx == 0) s -= C63;
                if (dx == 2) s -= C0;
                if (dy == 0 && dx == 0) s += xee;
                if (dy == 0 && dx == 2) s += xe0;
                if (dy == 2 && dx == 0) s += x0e;
                if (dy == 2 && dx == 2) s += x00;
                Sv[dy*3 + dx] = s;
            }
        #pragma unroll
        for (int j = 0; j < 2; ++j) {
            int u = TI[b][j];
            const float* wr = g_wsum + (size_t)u * KTOT + t*9;
            float p = 0.f;
            #pragma unroll
            for (int k = 0; k < 9; ++k) p = fmaf(wr[k], Sv[k], p);
            part[b*2 + j][t] = p;
        }
    }
    __syncthreads();

    {
        int w = t >> 5, l = t & 31;
        #pragma unroll
        for (int q = 0; q < 4; ++q) {
            int pr = w*4 + q;
            float s = part[pr][l] + part[pr][l+32] + part[pr][l+64] + part[pr][l+96];
            #pragma unroll
            for (int off = 16; off; off >>= 1) s += __shfl_down_sync(0xffffffffu, s, off);
            if (l == 0) {
                int bb2 = pr >> 1, jj = pr & 1;
                int u = TI[bb2][jj];
                m_s[bb2][u] += s * (1.0f/524288.0f);
            }
        }
    }
    __syncthreads();

    if (t < BB) {
        int b = t;
        float mx = -3.4e38f;
        for (int u = 0; u < UU; ++u) mx = fmaxf(mx, m_s[b][u]);
        float e[UU], s = 0.f;
        for (int u = 0; u < UU; ++u) { e[u] = expf(m_s[b][u] - mx); s += e[u]; }
        for (int u = 0; u < UU; ++u) g_gate[b*UU + u] = e[u] / s;
    }
}

// ---------------------------------------------------------------------------
// K3: W_eff + b_eff.  Writes k PERMUTED within each 8-group:
//   phys = (k & ~7) | ((k&3)<<1) | ((k&7)>>2)
// so fragment column pairs (tig, tig+4) are physically adjacent.
// ---------------------------------------------------------------------------
__global__ void k_weff(const float* __restrict__ conv_w, const float* __restrict__ conv_b)
{
    int b  = blockIdx.x >> 7;
    int co = blockIdx.x & 127;
    int t  = threadIdx.x;          // 128
    int u0 = g_topi[b*2], u1 = g_topi[b*2+1];
    float g0 = g_gate[b*UU + u0], g1 = g_gate[b*UU + u1];
    const float* w0 = conv_w + (size_t)(u0*CC + co) * KTOT;
    const float* w1 = conv_w + (size_t)(u1*CC + co) * KTOT;
    float* dst = g_Weff + (size_t)(b*CC + co) * KTOT;
    #pragma unroll
    for (int j = 0; j < 9; ++j) {
        int k = j*128 + t;
        float v = tf32r(g0 * tf32r(w0[k]) + g1 * tf32r(w1[k]));
        int pos = (k & ~7) | ((k & 3) << 1) | ((k & 7) >> 2);
        dst[pos] = v;
    }
    if (t == 0) {
        float s = 0.f;
        for (int u = 0; u < UU; ++u) s += g_gate[b*UU + u] * conv_b[u*CC + co];
        g_beff[b*CC + co] = s;
    }
}

// ---------------------------------------------------------------------------
// K4: tf32 mma.sync implicit-GEMM conv, permuted-k layout, LDS.64 fragments
// grid 256 = 8 b x 32 tiles (128 px); 256 thr = 8 warps (2m x 4n)
// ---------------------------------------------------------------------------
__global__ void __launch_bounds__(256) k_conv_mma(const float* __restrict__ xg,
                                                  float* __restrict__ out)
{
    __shared__ float As[128*SS];      // A chunk: 128co x 32k(perm), stride 40
    __shared__ float Bs[128*SS];      // B chunk: 128px x 32k(perm), stride 40

    int tid  = threadIdx.x;
    int lane = tid & 31, wid = tid >> 5;
    int b    = blockIdx.x >> 5;
    int tile = blockIdx.x & 31;
    int warp_m = wid >> 2;
    int warp_n = wid & 3;
    int gid = lane >> 2, tig = lane & 3;

    const float* xb = xg + (size_t)b * (CC*HW);
    const float* Wb = g_Weff + (size_t)b * (CC*KTOT);

    int n  = tid & 127;
    int kh = tid >> 7;
    int py = tile*2 + (n >> 6);
    int px = n & 63;

    float d[16][4];
    #pragma unroll
    for (int i = 0; i < 16; ++i)
        #pragma unroll
        for (int j = 0; j < 4; ++j) d[i][j] = 0.f;

    #pragma unroll 1
    for (int c = 0; c < CH; ++c) {
        __syncthreads();
        // A: 128co x 32k coalesced (permutation already applied in gmem)
        #pragma unroll
        for (int i = 0; i < 4; ++i) {
            int e  = tid + i*256;
            int co = e >> 3;
            int kq = (e & 7) * 4;
            float4 v = *(const float4*)(Wb + (size_t)co*KTOT + c*32 + kq);
            *(float4*)(As + co*SS + kq) = v;
        }
        // B: im2col 16 k-values (physical order; invperm folded into k calc)
        {
            int kb = c*32 + kh*16;
            #pragma unroll
            for (int g = 0; g < 4; ++g) {
                float v[4];
                #pragma unroll
                for (int e4 = 0; e4 < 4; ++e4) {
                    int e = g*4 + e4;
                    int p = e & 7;
                    int k = kb + (e & ~7) + (((p & 1) << 2) | (p >> 1));
                    int ci = (k * 7282) >> 16;       // k/9
                    int r  = k - ci*9;
                    int dy = (r * 11) >> 5;          // r/3
                    int dx = r - dy*3 - 1;
                    dy -= 1;
                    int yy = py + dy, xx = px + dx;
                    float val = 0.f;
                    if ((unsigned)yy < 64u && (unsigned)xx < 64u)
                        val = xb[((size_t)ci << 12) + (yy << 6) + xx];
                    v[e4] = tf32r(val);
                }
                *(float4*)(Bs + n*SS + kh*16 + g*4) =
                    make_float4(v[0], v[1], v[2], v[3]);
            }
        }
        __syncthreads();

        #pragma unroll
        for (int ks = 0; ks < 4; ++ks) {
            uint32_t af[4][4];
            #pragma unroll
            for (int mt = 0; mt < 4; ++mt) {
                int row = warp_m*64 + mt*16 + gid;
                int col = ks*8 + tig*2;
                float2 lo = *(const float2*)(As + row*SS + col);
                float2 hi = *(const float2*)(As + (row+8)*SS + col);
                af[mt][0] = __float_as_uint(lo.x);
                af[mt][2] = __float_as_uint(lo.y);
                af[mt][1] = __float_as_uint(hi.x);
                af[mt][3] = __float_as_uint(hi.y);
            }
            uint32_t bf[4][2];
            #pragma unroll
            for (int nt = 0; nt < 4; ++nt) {
                int nn = warp_n*32 + nt*8 + gid;
                float2 bb = *(const float2*)(Bs + nn*SS + ks*8 + tig*2);
                bf[nt][0] = __float_as_uint(bb.x);
                bf[nt][1] = __float_as_uint(bb.y);
            }
            #pragma unroll
            for (int mt = 0; mt < 4; ++mt)
                #pragma unroll
                for (int nt = 0; nt < 4; ++nt)
                    mma168(d[mt*4 + nt], af[mt], bf[nt]);
        }
    }

    // epilogue
    #pragma unroll
    for (int mt = 0; mt < 4; ++mt) {
        int co = warp_m*64 + mt*16 + gid;
        float be0 = g_beff[b*CC + co];
        float be8 = g_beff[b*CC + co + 8];
        #pragma unroll
        for (int nt = 0; nt < 4; ++nt) {
            int col = warp_n*32 + nt*8 + tig*2;
            float* op = out + (size_t)(b*CC + co) * HW + tile*128 + col;
            *(float2*)op = make_float2(d[mt*4+nt][0] + be0, d[mt*4+nt][1] + be0);
            *(float2*)(op + 8*HW) = make_float2(d[mt*4+nt][2] + be8, d[mt*4+nt][3] + be8);
        }
    }
}

// ---------------------------------------------------------------------------
// Host: JAX threefry2x32 noise (partitionable), key(42)
// ---------------------------------------------------------------------------
static inline uint32_t rotl32(uint32_t x, int d) { return (x << d) | (x >> (32 - d)); }

static void threefry2x32_host(uint32_t k0, uint32_t k1, uint32_t x0, uint32_t x1,
                              uint32_t* o0, uint32_t* o1)
{
    const uint32_t ks0 = k0, ks1 = k1, ks2 = k0 ^ k1 ^ 0x1BD11BDAu;
    const int ra[4] = {13, 15, 26, 6};
    const int rb[4] = {17, 29, 16, 24};
    x0 += ks0; x1 += ks1;
    for (int i = 0; i < 4; ++i) { x0 += x1; x1 = rotl32(x1, ra[i]); x1 ^= x0; }
    x0 += ks1; x1 += ks2 + 1u;
    for (int i = 0; i < 4; ++i) { x0 += x1; x1 = rotl32(x1, rb[i]); x1 ^= x0; }
    x0 += ks2; x1 += ks0 + 2u;
    for (int i = 0; i < 4; ++i) { x0 += x1; x1 = rotl32(x1, ra[i]); x1 ^= x0; }
    x0 += ks0; x1 += ks1 + 3u;
    for (int i = 0; i < 4; ++i) { x0 += x1; x1 = rotl32(x1, rb[i]); x1 ^= x0; }
    x0 += ks1; x1 += ks2 + 4u;
    for (int i = 0; i < 4; ++i) { x0 += x1; x1 = rotl32(x1, ra[i]); x1 ^= x0; }
    x0 += ks2; x1 += ks0 + 5u;
    *o0 = x0; *o1 = x1;
}

static double erfinv_host(double x)
{
    double p;
    double ww = -log((1.0 - x) * (1.0 + x));
    if (ww < 5.0) {
        ww -= 2.5;
        p = 2.81022636e-08;        p = 3.43273939e-07 + p*ww;
        p = -3.5233877e-06 + p*ww; p = -4.39150654e-06 + p*ww;
        p = 0.00021858087 + p*ww;  p = -0.00125372503 + p*ww;
        p = -0.00417768164 + p*ww; p = 0.246640727 + p*ww;
        p = 1.50140941 + p*ww;
    } else {
        ww = sqrt(ww) - 3.0;
        p = -0.000200214257;       p = 0.000100950558 + p*ww;
        p = 0.00134934322 + p*ww;  p = -0.00367342844 + p*ww;
        p = 0.00573950773 + p*ww;  p = -0.0076224613 + p*ww;
        p = 0.00943887047 + p*ww;  p = 1.00167406 + p*ww;
        p = 2.83297682 + p*ww;
    }
    return p * x;
}

static void compute_noise(float* noise /*64*/)
{
    float lo = nextafterf(-1.0f, 0.0f);
    float range = 1.0f - lo;
    for (uint32_t i = 0; i < 64; ++i) {
        uint32_t o0, o1;
        threefry2x32_host(0u, 42u, 0u, i, &o0, &o1);
        uint32_t bits = o0 ^ o1;
        uint32_t fb = (bits >> 9) | 0x3f800000u;
        float f; memcpy(&f, &fb, 4);
        f -= 1.0f;
        float u = f * range + lo;
        if (u < lo) u = lo;
        double z = erfinv_host((double)u);
        noise[i] = (float)(sqrt(2.0) * z) * 0.01f;
    }
}

// ---------------------------------------------------------------------------
// Entry — inputs resolved BY SIZE
// ---------------------------------------------------------------------------
static const float* find_by_size(void* const* d_in, const int* in_sizes, int n_in,
                                 int want, int occurrence)
{
    int seen = 0;
    for (int i = 0; i < n_in; ++i) {
        if (in_sizes[i] == want) {
            if (seen == occurrence) return (const float*)d_in[i];
            ++seen;
        }
    }
    return nullptr;
}

extern "C" void kernel_launch(void* const* d_in, const int* in_sizes, int n_in,
                              void* d_out, int out_size)
{
    const float* x      = find_by_size(d_in, in_sizes, n_in, BB*CC*HW, 0);
    const float* W1     = find_by_size(d_in, in_sizes, n_in, 16384, 0);
    const float* W2     = find_by_size(d_in, in_sizes, n_in, 16384, 1);
    const float* b1     = find_by_size(d_in, in_sizes, n_in, 128, 0);
    const float* b2     = find_by_size(d_in, in_sizes, n_in, 128, 1);
    const float* W3     = find_by_size(d_in, in_sizes, n_in, 8192, 0);
    const float* b3     = find_by_size(d_in, in_sizes, n_in, 64, 0);
    const float* W4     = find_by_size(d_in, in_sizes, n_in, 4096, 0);
    const float* b4     = find_by_size(d_in, in_sizes, n_in, 64, 1);
    const float* Wu     = find_by_size(d_in, in_sizes, n_in, 512, 0);
    const float* bu     = find_by_size(d_in, in_sizes, n_in, 8, 0);
    const float* Wc     = find_by_size(d_in, in_sizes, n_in, 640, 0);
    const float* bc     = find_by_size(d_in, in_sizes, n_in, 10, 0);
    const float* conv_w = find_by_size(d_in, in_sizes, n_in, UU*CC*CC*9, 0);
    const float* conv_b = find_by_size(d_in, in_sizes, n_in, 1024, 0);
    float* out = (float*)d_out;

    if (!x || !W1 || !W2 || !b1 || !b2 || !W3 || !b3 || !W4 || !b4 ||
        !Wu || !bu || !Wc || !bc || !conv_w || !conv_b) {
        x = (const float*)d_in[0];
        W1 = (const float*)d_in[1];  b1 = (const float*)d_in[2];
        W2 = (const float*)d_in[3];  b2 = (const float*)d_in[4];
        W3 = (const float*)d_in[5];  b3 = (const float*)d_in[6];
        W4 = (const float*)d_in[7];  b4 = (const float*)d_in[8];
        Wu = (const float*)d_in[9];  bu = (const float*)d_in[10];
        Wc = (const float*)d_in[11]; bc = (const float*)d_in[12];
        conv_w = (const float*)d_in[13]; conv_b = (const float*)d_in[14];
    }

    Noise64 nz;
    compute_noise(nz.v);

    L2Args la;
    const float* l2p[12] = {W1,b1,W2,b2,W3,b3,W4,b4,Wu,bu,Wc,bc};
    const int    l2n[12] = {16384,128,16384,128,8192,64,4096,64,512,8,640,10};
    for (int i = 0; i < 12; ++i) { la.p[i] = l2p[i]; la.n[i] = l2n[i]; }

    k_pre<<<1076, 256>>>(x, conv_w, la);
    k_router<<<1, 128>>>(W1, b1, W2, b2, W3, b3, W4, b4,
                         Wu, bu, Wc, bc, conv_b, nz, out);
    k_weff<<<1024, 128>>>(conv_w, conv_b);
    k_conv_mma<<<256, 256>>>(x, out);
}

// round 17
// speedup vs baseline: 1.1556x; 1.0925x over previous
#include <cuda_runtime.h>
#include <cuda_bf16.h>
#include <math.h>
#include <string.h>
#include <stdint.h>

// ---------------------------------------------------------------------------
// Problem constants
// ---------------------------------------------------------------------------
#define BB 8
#define CC 128
#define HH 64
#define WW 64
#define UU 8
#define TOPK 2
#define LL 10
#define HID 128

#define HW (HH*WW)                       // 4096
#define N_FINAL (BB*CC*HW)               // 4194304
#define OFF_CLS  (N_FINAL)
#define OFF_L2   (N_FINAL + 80)
#define OFF_TOPI (N_FINAL + 81)
#define OFF_LB   (N_FINAL + 97)

#define KTOT 1152                        // 128 ci * 9
#define CST  264                         // Xs ci stride: 4 rows * 66 cols
#define AST  40                          // As row stride (pad 32 -> 40)

// ---------------------------------------------------------------------------
// Device scratch
// ---------------------------------------------------------------------------
__device__ float g_stats[BB*CC*9];
__device__ float g_wsum[UU*CC*9];
__device__ float g_norms[12];
__device__ int   g_topi[BB*2];
__device__ float g_gate[BB*UU];
__device__ float g_beff[BB*CC];
// [b][co][chunk(4)][shift(9)][ci32 pair-permuted]
__device__ float g_Weff[BB*CC*KTOT];

// TF32 rounding
__device__ __forceinline__ float tf32r(float v)
{
    uint32_t r;
    asm("cvt.rna.tf32.f32 %0, %1;" : "=r"(r) : "f"(v));
    float f;
    asm("mov.b32 %0, %1;" : "=f"(f) : "r"(r));
    return f;
}

// portable warp-level tf32 MMA (sm_80+)
__device__ __forceinline__ void mma168(float* d, const uint32_t* a, const uint32_t* bf)
{
    asm volatile(
        "mma.sync.aligned.m16n8k8.row.col.f32.tf32.tf32.f32 "
        "{%0,%1,%2,%3}, {%4,%5,%6,%7}, {%8,%9}, {%0,%1,%2,%3};"
        : "+f"(d[0]), "+f"(d[1]), "+f"(d[2]), "+f"(d[3])
        : "r"(a[0]), "r"(a[1]), "r"(a[2]), "r"(a[3]), "r"(bf[0]), "r"(bf[1]));
}

// ---------------------------------------------------------------------------
// K1 (fused pre-pass): [0,1024) stats; [1024,1064) wsum; [1064,1076) l2
// ---------------------------------------------------------------------------
struct L2Args { const float* p[12]; int n[12]; };

__global__ void __launch_bounds__(256) k_pre(const float* __restrict__ x,
                                             const float* __restrict__ conv_w,
                                             L2Args a)
{
    int blk = blockIdx.x;
    int t   = threadIdx.x;

    if (blk < 1024) {
        const float* base = x + (size_t)blk * HW;
        float T=0.f, r0=0.f, r63=0.f, c0=0.f, c63=0.f;
        for (int i = t; i < HW; i += 256) {
            float v = base[i];
            int y = i >> 6, xc = i & 63;
            T += v;
            if (y == 0)   r0  += v;
            if (y == 63)  r63 += v;
            if (xc == 0)  c0  += v;
            if (xc == 63) c63 += v;
        }
        #pragma unroll
        for (int off = 16; off; off >>= 1) {
            T   += __shfl_down_sync(0xffffffffu, T,   off);
            r0  += __shfl_down_sync(0xffffffffu, r0,  off);
            r63 += __shfl_down_sync(0xffffffffu, r63, off);
            c0  += __shfl_down_sync(0xffffffffu, c0,  off);
            c63 += __shfl_down_sync(0xffffffffu, c63, off);
        }
        __shared__ float red[8][5];
        if ((t & 31) == 0) {
            int w = t >> 5;
            red[w][0]=T; red[w][1]=r0; red[w][2]=r63; red[w][3]=c0; red[w][4]=c63;
        }
        __syncthreads();
        if (t == 0) {
            float s[5] = {0,0,0,0,0};
            for (int w = 0; w < 8; ++w)
                for (int k = 0; k < 5; ++k) s[k] += red[w][k];
            float* o = g_stats + (size_t)blk * 9;
            o[0]=s[0]; o[1]=s[1]; o[2]=s[2]; o[3]=s[3]; o[4]=s[4];
            o[5]=base[0]; o[6]=base[63]; o[7]=base[63*64]; o[8]=base[HW-1];
        }
    } else if (blk < 1064) {
        int q = blk - 1024;
        int u = q / 5;
        int idx = (q % 5) * 256 + t;
        if (idx < KTOT) {
            const float* base = conv_w + (size_t)u * CC * KTOT + idx;
            float s = 0.f;
            for (int co = 0; co < CC; ++co) s += base[(size_t)co * KTOT];
            g_wsum[u * KTOT + idx] = s;
        }
    } else {
        int bi = blk - 1064;
        const float* p = a.p[bi]; int n = a.n[bi];
        float s = 0.f;
        for (int i = t; i < n; i += 256) { float v = p[i]; s += v*v; }
        #pragma unroll
        for (int off = 16; off; off >>= 1) s += __shfl_down_sync(0xffffffffu, s, off);
        __shared__ float ws[8];
        if ((t & 31) == 0) ws[t >> 5] = s;
        __syncthreads();
        if (t == 0) {
            float tot = 0.f;
            for (int w = 0; w < 8; ++w) tot += ws[w];
            g_norms[bi] = sqrtf(tot);
        }
    }
}

// ---------------------------------------------------------------------------
// K2: router (1 block, 128 thr)
// ---------------------------------------------------------------------------
struct Noise64 { float v[64]; };

__global__ void k_router(const float* __restrict__ W1, const float* __restrict__ b1,
                         const float* __restrict__ W2, const float* __restrict__ b2,
                         const float* __restrict__ W3, const float* __restrict__ b3,
                         const float* __restrict__ W4, const float* __restrict__ b4,
                         const float* __restrict__ Wu, const float* __restrict__ bu,
                         const float* __restrict__ Wc, const float* __restrict__ bc,
                         const float* __restrict__ conv_b,
                         Noise64 nz, float* __restrict__ out)
{
    __shared__ float A[BB][HID];
    __shared__ float Bv[BB][HID];
    __shared__ float F[BB][64];
    __shared__ float S[BB][UU];
    __shared__ int   TI[BB][2];
    __shared__ float bsum_s[UU];
    __shared__ float m_s[BB][UU];
    __shared__ float part[16][128];
    __shared__ float wu_s[512];
    __shared__ float wc_s[640];
    __shared__ float cb_s[1024];

    int t = threadIdx.x;   // 128

    for (int i = t; i < 512;  i += 128) wu_s[i] = Wu[i];
    for (int i = t; i < 640;  i += 128) wc_s[i] = Wc[i];
    for (int i = t; i < 1024; i += 128) cb_s[i] = conv_b[i];
    for (int b = 0; b < BB; ++b)
        A[b][t] = g_stats[(size_t)(b*CC + t) * 9] * (1.0f/4096.0f);
    __syncthreads();

    // L1
    {
        const float4* Wv = (const float4*)W1;
        float acc[BB]; float bb = b1[t];
        #pragma unroll
        for (int b = 0; b < BB; ++b) acc[b] = bb;
        #pragma unroll 4
        for (int i = 0; i < 32; ++i) {
            float4 w = Wv[t*32 + i];
            int c = i*4;
            #pragma unroll
            for (int b = 0; b < BB; ++b) {
                acc[b] = fmaf(A[b][c+0], w.x, acc[b]);
                acc[b] = fmaf(A[b][c+1], w.y, acc[b]);
                acc[b] = fmaf(A[b][c+2], w.z, acc[b]);
                acc[b] = fmaf(A[b][c+3], w.w, acc[b]);
            }
        }
        #pragma unroll
        for (int b = 0; b < BB; ++b) Bv[b][t] = fmaxf(acc[b], 0.f);
    }
    __syncthreads();
    // L2
    {
        const float4* Wv = (const float4*)W2;
        float acc[BB]; float bb = b2[t];
        #pragma unroll
        for (int b = 0; b < BB; ++b) acc[b] = bb;
        #pragma unroll 4
        for (int i = 0; i < 32; ++i) {
            float4 w = Wv[t*32 + i];
            int c = i*4;
            #pragma unroll
            for (int b = 0; b < BB; ++b) {
                acc[b] = fmaf(Bv[b][c+0], w.x, acc[b]);
                acc[b] = fmaf(Bv[b][c+1], w.y, acc[b]);
                acc[b] = fmaf(Bv[b][c+2], w.z, acc[b]);
                acc[b] = fmaf(Bv[b][c+3], w.w, acc[b]);
            }
        }
        #pragma unroll
        for (int b = 0; b < BB; ++b) A[b][t] = fmaxf(acc[b], 0.f);
    }
    __syncthreads();
    // L3: 128 -> 64
    if (t < 64) {
        const float4* Wv = (const float4*)W3;
        float acc[BB]; float bb = b3[t];
        #pragma unroll
        for (int b = 0; b < BB; ++b) acc[b] = bb;
        #pragma unroll 4
        for (int i = 0; i < 32; ++i) {
            float4 w = Wv[t*32 + i];
            int c = i*4;
            #pragma unroll
            for (int b = 0; b < BB; ++b) {
                acc[b] = fmaf(A[b][c+0], w.x, acc[b]);
                acc[b] = fmaf(A[b][c+1], w.y, acc[b]);
                acc[b] = fmaf(A[b][c+2], w.z, acc[b]);
                acc[b] = fmaf(A[b][c+3], w.w, acc[b]);
            }
        }
        #pragma unroll
        for (int b = 0; b < BB; ++b) Bv[b][t] = fmaxf(acc[b], 0.f);
    }
    __syncthreads();
    // L4: 64 -> 64 (no relu)
    if (t < 64) {
        const float4* Wv = (const float4*)W4;
        float acc[BB]; float bb = b4[t];
        #pragma unroll
        for (int b = 0; b < BB; ++b) acc[b] = bb;
        #pragma unroll 4
        for (int i = 0; i < 16; ++i) {
            float4 w = Wv[t*16 + i];
            int c = i*4;
            #pragma unroll
            for (int b = 0; b < BB; ++b) {
                acc[b] = fmaf(Bv[b][c+0], w.x, acc[b]);
                acc[b] = fmaf(Bv[b][c+1], w.y, acc[b]);
                acc[b] = fmaf(Bv[b][c+2], w.z, acc[b]);
                acc[b] = fmaf(Bv[b][c+3], w.w, acc[b]);
            }
        }
        #pragma unroll
        for (int b = 0; b < BB; ++b) F[b][t] = acc[b];
    }
    __syncthreads();

    if (t < BB*UU) {
        int b = t >> 3, u = t & 7;
        float a = bu[u] + nz.v[t];
        for (int c = 0; c < 64; ++c) a = fmaf(F[b][c], wu_s[u*64 + c], a);
        S[b][u] = a;
    }
    if (t < BB*LL) {
        int b = t / LL, l = t % LL;
        float a = bc[l];
        for (int c = 0; c < 64; ++c) a = fmaf(F[b][c], wc_s[l*64 + c], a);
        out[OFF_CLS + t] = a;
    }
    if (t >= 96 && t < 96 + UU) {
        int u = t - 96;
        float s = 0.f;
        for (int c = 0; c < CC; ++c) s += cb_s[u*CC + c];
        bsum_s[u] = s;
    }
    __syncthreads();

    if (t < BB) {
        int b = t;
        int i0 = 0; float v0 = S[b][0];
        for (int u = 1; u < UU; ++u) if (S[b][u] > v0) { v0 = S[b][u]; i0 = u; }
        int i1 = -1; float v1 = -3.4e38f;
        for (int u = 0; u < UU; ++u) if (u != i0 && S[b][u] > v1) { v1 = S[b][u]; i1 = u; }
        TI[b][0] = i0;  TI[b][1] = i1;
        g_topi[b*2] = i0;  g_topi[b*2+1] = i1;
        out[OFF_TOPI + b*2]     = (float)i0;
        out[OFF_TOPI + b*2 + 1] = (float)i1;
    }
    __syncthreads();

    if (t == 0) {
        int cnt[UU] = {0,0,0,0,0,0,0,0};
        for (int b = 0; b < BB; ++b) { cnt[TI[b][0]]++; cnt[TI[b][1]]++; }
        float lb = 0.f;
        for (int u = 0; u < UU; ++u) {
            float d = (float)cnt[u] * (1.0f/16.0f) - 0.125f;
            lb += d*d;
        }
        out[OFF_LB] = lb * (1.0f/8.0f);
        float s = 0.f;
        for (int i = 0; i < 12; ++i) s += g_norms[i];
        out[OFF_L2] = 0.01f * s;
    }
    if (t < BB*UU) m_s[t>>3][t&7] = bsum_s[t&7] * (1.0f/128.0f);

    for (int b = 0; b < BB; ++b) {
        const float* st = g_stats + (size_t)(b*CC + t) * 9;
        float T  = st[0], R0 = st[1], R63 = st[2], C0 = st[3], C63 = st[4];
        float x00 = st[5], x0e = st[6], xe0 = st[7], xee = st[8];
        float Sv[9];
        #pragma unroll
        for (int dy = 0; dy < 3; ++dy)
            #pragma unroll
            for (int dx = 0; dx < 3; ++dx) {
                float s = T;
                if (dy == 0) s -= R63;
                if (dy == 2) s -= R0;
                if (dx == 0) s -= C63;
                if (dx == 2) s -= C0;
                if (dy == 0 && dx == 0) s += xee;
                if (dy == 0 && dx == 2) s += xe0;
                if (dy == 2 && dx == 0) s += x0e;
                if (dy == 2 && dx == 2) s += x00;
                Sv[dy*3 + dx] = s;
            }
        #pragma unroll
        for (int j = 0; j < 2; ++j) {
            int u = TI[b][j];
            const float* wr = g_wsum + (size_t)u * KTOT + t*9;
            float p = 0.f;
            #pragma unroll
            for (int k = 0; k < 9; ++k) p = fmaf(wr[k], Sv[k], p);
            part[b*2 + j][t] = p;
        }
    }
    __syncthreads();

    {
        int w = t >> 5, l = t & 31;
        #pragma unroll
        for (int q = 0; q < 4; ++q) {
            int pr = w*4 + q;
            float s = part[pr][l] + part[pr][l+32] + part[pr][l+64] + part[pr][l+96];
            #pragma unroll
            for (int off = 16; off; off >>= 1) s += __shfl_down_sync(0xffffffffu, s, off);
            if (l == 0) {
                int bb2 = pr >> 1, jj = pr & 1;
                int u = TI[bb2][jj];
                m_s[bb2][u] += s * (1.0f/524288.0f);
            }
        }
    }
    __syncthreads();

    if (t < BB) {
        int b = t;
        float mx = -3.4e38f;
        for (int u = 0; u < UU; ++u) mx = fmaxf(mx, m_s[b][u]);
        float e[UU], s = 0.f;
        for (int u = 0; u < UU; ++u) { e[u] = expf(m_s[b][u] - mx); s += e[u]; }
        for (int u = 0; u < UU; ++u) g_gate[b*UU + u] = e[u] / s;
    }
}

// ---------------------------------------------------------------------------
// K3: W_eff + b_eff. Layout: [chunk cc][shift r][ci32 pair-permuted]:
//   pos = cc*288 + r*32 + pairperm(ci & 31)
// ---------------------------------------------------------------------------
__global__ void k_weff(const float* __restrict__ conv_w, const float* __restrict__ conv_b)
{
    int b  = blockIdx.x >> 7;
    int co = blockIdx.x & 127;
    int t  = threadIdx.x;          // 128
    int u0 = g_topi[b*2], u1 = g_topi[b*2+1];
    float g0 = g_gate[b*UU + u0], g1 = g_gate[b*UU + u1];
    const float* w0 = conv_w + (size_t)(u0*CC + co) * KTOT;
    const float* w1 = conv_w + (size_t)(u1*CC + co) * KTOT;
    float* dst = g_Weff + (size_t)(b*CC + co) * KTOT;
    #pragma unroll
    for (int j = 0; j < 9; ++j) {
        int k = j*128 + t;
        float v = tf32r(g0 * tf32r(w0[k]) + g1 * tf32r(w1[k]));
        int ci = (k * 7282) >> 16;          // k/9
        int r  = k - ci*9;
        int cc = ci >> 5, cin = ci & 31;
        int pp = (cin & ~7) | ((cin & 3) << 1) | ((cin & 7) >> 2);
        dst[cc*288 + r*32 + pp] = v;
    }
    if (t == 0) {
        float s = 0.f;
        for (int u = 0; u < UU; ++u) s += g_gate[b*UU + u] * conv_b[u*CC + co];
        g_beff[b*CC + co] = s;
    }
}

// ---------------------------------------------------------------------------
// K4: tf32 mma.sync conv — shift-decomposed K: stage x-tile per ci-chunk,
// 9 shift phases read B fragments directly from the x-tile (no im2col).
// grid 256 = 8 b x 32 tiles (128 px); 256 thr = 8 warps (2m x 4n)
// ---------------------------------------------------------------------------
__global__ void __launch_bounds__(256) k_conv_mma(const float* __restrict__ xg,
                                                  float* __restrict__ out)
{
    __shared__ float Xs[32*CST];      // 8448: [ci32][row4][col66], tf32-rounded
    __shared__ float As[128*AST];     // A: 128co x 32ci (pair-perm), stride 40

    int tid  = threadIdx.x;
    int lane = tid & 31, wid = tid >> 5;
    int b    = blockIdx.x >> 5;
    int tile = blockIdx.x & 31;
    int warp_m = wid >> 2;
    int warp_n = wid & 3;
    int gid = lane >> 2, tig = lane & 3;

    const float* xb = xg + (size_t)b * (CC*HW);
    const float* Wb = g_Weff + (size_t)b * (CC*KTOT);

    float d[16][4];
    #pragma unroll
    for (int i = 0; i < 16; ++i)
        #pragma unroll
        for (int j = 0; j < 4; ++j) d[i][j] = 0.f;

    // per-thread B pixel bases (row in {0,1}, col in 0..63)
    int nbase[4];
    #pragma unroll
    for (int nt = 0; nt < 4; ++nt) {
        int nn = warp_n*32 + nt*8 + gid;
        nbase[nt] = (nn >> 6) * 66 + (nn & 63);
    }

    #pragma unroll 1
    for (int cc = 0; cc < 4; ++cc) {
        __syncthreads();
        // ---- stage x-tile: 32 ci x 4 rows x 66 cols (halo, zero-padded) ----
        #pragma unroll 1
        for (int p = wid; p < 128; p += 8) {
            int ci = p >> 2, rw = p & 3;
            int ty = tile*2 - 1 + rw;
            const float* src = xb + (((size_t)(cc*32 + ci)) << 12) + ((size_t)(ty & 63) << 6);
            float* dstp = Xs + ci*CST + rw*66;
            bool rok = (unsigned)ty < 64u;
            #pragma unroll
            for (int c0 = 0; c0 < 96; c0 += 32) {
                int col = c0 + lane;
                if (col < 66) {
                    int gx = col - 1;
                    float v = (rok && (unsigned)gx < 64u) ? src[gx] : 0.f;
                    dstp[col] = tf32r(v);
                }
            }
        }

        #pragma unroll 1
        for (int r = 0; r < 9; ++r) {
            __syncthreads();
            // ---- stage A (cc, r): 128co x 32ci ----
            #pragma unroll
            for (int i = 0; i < 4; ++i) {
                int e  = tid + i*256;
                int co = e >> 3;
                int kq = (e & 7) * 4;
                float4 v = *(const float4*)(Wb + (size_t)co*KTOT + cc*288 + r*32 + kq);
                *(float4*)(As + co*AST + kq) = v;
            }
            __syncthreads();

            int dy = (r*11) >> 5;            // r/3
            int dx = r - dy*3;
            int shift = dy*66 + dx;
            int bb[4];
            #pragma unroll
            for (int nt = 0; nt < 4; ++nt) bb[nt] = nbase[nt] + shift;
            const float* Xt = Xs + tig*CST;

            #pragma unroll
            for (int ks = 0; ks < 4; ++ks) {
                uint32_t af[4][4];
                #pragma unroll
                for (int mt = 0; mt < 4; ++mt) {
                    int row = warp_m*64 + mt*16 + gid;
                    int col = ks*8 + tig*2;
                    float2 lo = *(const float2*)(As + row*AST + col);
                    float2 hi = *(const float2*)(As + (row+8)*AST + col);
                    af[mt][0] = __float_as_uint(lo.x);
                    af[mt][2] = __float_as_uint(lo.y);
                    af[mt][1] = __float_as_uint(hi.x);
                    af[mt][3] = __float_as_uint(hi.y);
                }
                const float* Xk = Xt + ks*8*CST;
                uint32_t bf[4][2];
                #pragma unroll
                for (int nt = 0; nt < 4; ++nt) {
                    bf[nt][0] = __float_as_uint(Xk[bb[nt]]);
                    bf[nt][1] = __float_as_uint(Xk[bb[nt] + 4*CST]);
                }
                #pragma unroll
                for (int mt = 0; mt < 4; ++mt)
                    #pragma unroll
                    for (int nt = 0; nt < 4; ++nt)
                        mma168(d[mt*4 + nt], af[mt], bf[nt]);
            }
        }
    }

    // epilogue
    #pragma unroll
    for (int mt = 0; mt < 4; ++mt) {
        int co = warp_m*64 + mt*16 + gid;
        float be0 = g_beff[b*CC + co];
        float be8 = g_beff[b*CC + co + 8];
        #pragma unroll
        for (int nt = 0; nt < 4; ++nt) {
            int col = warp_n*32 + nt*8 + tig*2;
            float* op = out + (size_t)(b*CC + co) * HW + tile*128 + col;
            *(float2*)op = make_float2(d[mt*4+nt][0] + be0, d[mt*4+nt][1] + be0);
            *(float2*)(op + 8*HW) = make_float2(d[mt*4+nt][2] + be8, d[mt*4+nt][3] + be8);
        }
    }
}

// ---------------------------------------------------------------------------
// Host: JAX threefry2x32 noise (partitionable), key(42)
// ---------------------------------------------------------------------------
static inline uint32_t rotl32(uint32_t x, int d) { return (x << d) | (x >> (32 - d)); }

static void threefry2x32_host(uint32_t k0, uint32_t k1, uint32_t x0, uint32_t x1,
                              uint32_t* o0, uint32_t* o1)
{
    const uint32_t ks0 = k0, ks1 = k1, ks2 = k0 ^ k1 ^ 0x1BD11BDAu;
    const int ra[4] = {13, 15, 26, 6};
    const int rb[4] = {17, 29, 16, 24};
    x0 += ks0; x1 += ks1;
    for (int i = 0; i < 4; ++i) { x0 += x1; x1 = rotl32(x1, ra[i]); x1 ^= x0; }
    x0 += ks1; x1 += ks2 + 1u;
    for (int i = 0; i < 4; ++i) { x0 += x1; x1 = rotl32(x1, rb[i]); x1 ^= x0; }
    x0 += ks2; x1 += ks0 + 2u;
    for (int i = 0; i < 4; ++i) { x0 += x1; x1 = rotl32(x1, ra[i]); x1 ^= x0; }
    x0 += ks0; x1 += ks1 + 3u;
    for (int i = 0; i < 4; ++i) { x0 += x1; x1 = rotl32(x1, rb[i]); x1 ^= x0; }
    x0 += ks1; x1 += ks2 + 4u;
    for (int i = 0; i < 4; ++i) { x0 += x1; x1 = rotl32(x1, ra[i]); x1 ^= x0; }
    x0 += ks2; x1 += ks0 + 5u;
    *o0 = x0; *o1 = x1;
}

static double erfinv_host(double x)
{
    double p;
    double ww = -log((1.0 - x) * (1.0 + x));
    if (ww < 5.0) {
        ww -= 2.5;
        p = 2.81022636e-08;        p = 3.43273939e-07 + p*ww;
        p = -3.5233877e-06 + p*ww; p = -4.39150654e-06 + p*ww;
        p = 0.00021858087 + p*ww;  p = -0.00125372503 + p*ww;
        p = -0.00417768164 + p*ww; p = 0.246640727 + p*ww;
        p = 1.50140941 + p*ww;
    } else {
        ww = sqrt(ww) - 3.0;
        p = -0.000200214257;       p = 0.000100950558 + p*ww;
        p = 0.00134934322 + p*ww;  p = -0.00367342844 + p*ww;
        p = 0.00573950773 + p*ww;  p = -0.0076224613 + p*ww;
        p = 0.00943887047 + p*ww;  p = 1.00167406 + p*ww;
        p = 2.83297682 + p*ww;
    }
    return p * x;
}

static void compute_noise(float* noise /*64*/)
{
    float lo = nextafterf(-1.0f, 0.0f);
    float range = 1.0f - lo;
    for (uint32_t i = 0; i < 64; ++i) {
        uint32_t o0, o1;
        threefry2x32_host(0u, 42u, 0u, i, &o0, &o1);
        uint32_t bits = o0 ^ o1;
        uint32_t fb = (bits >> 9) | 0x3f800000u;
        float f; memcpy(&f, &fb, 4);
        f -= 1.0f;
        float u = f * range + lo;
        if (u < lo) u = lo;
        double z = erfinv_host((double)u);
        noise[i] = (float)(sqrt(2.0) * z) * 0.01f;
    }
}

// ---------------------------------------------------------------------------
// Entry — inputs resolved BY SIZE
// ---------------------------------------------------------------------------
static const float* find_by_size(void* const* d_in, const int* in_sizes, int n_in,
                                 int want, int occurrence)
{
    int seen = 0;
    for (int i = 0; i < n_in; ++i) {
        if (in_sizes[i] == want) {
            if (seen == occurrence) return (const float*)d_in[i];
            ++seen;
        }
    }
    return nullptr;
}

extern "C" void kernel_launch(void* const* d_in, const int* in_sizes, int n_in,
                              void* d_out, int out_size)
{
    const float* x      = find_by_size(d_in, in_sizes, n_in, BB*CC*HW, 0);
    const float* W1     = find_by_size(d_in, in_sizes, n_in, 16384, 0);
    const float* W2     = find_by_size(d_in, in_sizes, n_in, 16384, 1);
    const float* b1     = find_by_size(d_in, in_sizes, n_in, 128, 0);
    const float* b2     = find_by_size(d_in, in_sizes, n_in, 128, 1);
    const float* W3     = find_by_size(d_in, in_sizes, n_in, 8192, 0);
    const float* b3     = find_by_size(d_in, in_sizes, n_in, 64, 0);
    const float* W4     = find_by_size(d_in, in_sizes, n_in, 4096, 0);
    const float* b4     = find_by_size(d_in, in_sizes, n_in, 64, 1);
    const float* Wu     = find_by_size(d_in, in_sizes, n_in, 512, 0);
    const float* bu     = find_by_size(d_in, in_sizes, n_in, 8, 0);
    const float* Wc     = find_by_size(d_in, in_sizes, n_in, 640, 0);
    const float* bc     = find_by_size(d_in, in_sizes, n_in, 10, 0);
    const float* conv_w = find_by_size(d_in, in_sizes, n_in, UU*CC*CC*9, 0);
    const float* conv_b = find_by_size(d_in, in_sizes, n_in, 1024, 0);
    float* out = (float*)d_out;

    if (!x || !W1 || !W2 || !b1 || !b2 || !W3 || !b3 || !W4 || !b4 ||
        !Wu || !bu || !Wc || !bc || !conv_w || !conv_b) {
        x = (const float*)d_in[0];
        W1 = (const float*)d_in[1];  b1 = (const float*)d_in[2];
        W2 = (const float*)d_in[3];  b2 = (const float*)d_in[4];
        W3 = (const float*)d_in[5];  b3 = (const float*)d_in[6];
        W4 = (const float*)d_in[7];  b4 = (const float*)d_in[8];
        Wu = (const float*)d_in[9];  bu = (const float*)d_in[10];
        Wc = (const float*)d_in[11]; bc = (const float*)d_in[12];
        conv_w = (const float*)d_in[13]; conv_b = (const float*)d_in[14];
    }

    Noise64 nz;
    compute_noise(nz.v);

    L2Args la;
    const float* l2p[12] = {W1,b1,W2,b2,W3,b3,W4,b4,Wu,bu,Wc,bc};
    const int    l2n[12] = {16384,128,16384,128,8192,64,4096,64,512,8,640,10};
    for (int i = 0; i < 12; ++i) { la.p[i] = l2p[i]; la.n[i] = l2n[i]; }

    k_pre<<<1076, 256>>>(x, conv_w, la);
    k_router<<<1, 128>>>(W1, b1, W2, b2, W3, b3, W4, b4,
                         Wu, bu, Wc, bc, conv_b, nz, out);
    k_weff<<<1024, 128>>>(conv_w, conv_b);
    k_conv_mma<<<256, 256>>>(x, out);
}